// round 1
// baseline (speedup 1.0000x reference)
#include <cuda_runtime.h>
#include <math.h>
#include <stdint.h>

// Problem dims
#define NB 8
#define NC 512
#define NL 8192
#define NA 7
#define NPA (NL*NA)          // 57344 anchors per batch
#define PRE_K 600
#define POST_K 100
#define NMW 19               // ceil(600/32)

// Output layout (concatenation of the reference tuple, row-major, f32)
#define SZ_OBJ   (NB*NPA)                  // 458752
#define OFF_OBJ  0
#define OFF_REG  (SZ_OBJ)                  // 458752
#define SZ_REG   (NB*NPA*2)                // 917504
#define OFF_ANCH (OFF_REG + SZ_REG)        // 1376256
#define SZ_ANCH  (NPA*2)                   // 114688
#define OFF_PROPS (OFF_ANCH + SZ_ANCH)     // 1490944
#define SZ_PROPS (NB*POST_K*2)             // 1600
#define OFF_PSC  (OFF_PROPS + SZ_PROPS)    // 1492544
#define OFF_PMASK (OFF_PSC + NB*POST_K)    // 1493344

// Scratch (device globals; no allocation allowed)
__device__ float    g_h[(size_t)NB*NC*NL];        // conv output, 128MB
__device__ float    g_boxes[(size_t)NB*NPA*2];
__device__ float    g_scores[(size_t)NB*NPA];
__device__ unsigned g_mask[(size_t)NB*PRE_K*NMW];

__constant__ float c_lens[NA] = {1.f,2.f,3.f,4.f,5.f,7.f,9.f};

// ---------------------------------------------------------------------------
// Kernel 1: conv1d(k=3, pad=1) + bias + relu.  h[b][o][l]
// Tiled implicit GEMM: BM=128 (o), BN=128 (l), BK=8 (ci), 256 thr, 8x8 tiles
// ---------------------------------------------------------------------------
__global__ __launch_bounds__(256, 2)
void conv_kernel(const float* __restrict__ feat,
                 const float* __restrict__ w,
                 const float* __restrict__ bias) {
    const int b  = blockIdx.z;
    const int o0 = blockIdx.y * 128;
    const int l0 = blockIdx.x * 128;
    const int tid = threadIdx.x;
    const int tx = tid & 15;       // l dim
    const int ty = tid >> 4;       // o dim

    __shared__ float Ws[3*8*128];      // [t][kk][oo]
    __shared__ float Fs[8*132];        // [kk][j], j covers l0-1 .. l0+128 (130 used)

    float acc[8][8];
#pragma unroll
    for (int i = 0; i < 8; i++)
#pragma unroll
        for (int j = 0; j < 8; j++) acc[i][j] = 0.f;

    const float* fb = feat + (size_t)b*NC*NL;

    for (int c0 = 0; c0 < NC; c0 += 8) {
        // --- load W tile: 128 oo rows x 24 contiguous floats = 768 float4
#pragma unroll
        for (int r = 0; r < 3; r++) {
            int q = tid + 256*r;                 // 0..767
            int oo = q / 6, v = q % 6;
            const float4 w4 = *(const float4*)(w + (size_t)(o0+oo)*1536 + c0*3 + 4*v);
            int e = 4*v;
            Ws[((e  )%3)*1024 + ((e  )/3)*128 + oo] = w4.x;
            Ws[((e+1)%3)*1024 + ((e+1)/3)*128 + oo] = w4.y;
            Ws[((e+2)%3)*1024 + ((e+2)/3)*128 + oo] = w4.z;
            Ws[((e+3)%3)*1024 + ((e+3)/3)*128 + oo] = w4.w;
        }
        // --- load F tile: 8 rows x 130 cols
        {
            int row = tid >> 5, lane = tid & 31;
            const float* fr = fb + (size_t)(c0+row)*NL;
#pragma unroll
            for (int jj = lane; jj < 130; jj += 32) {
                int gl = l0 - 1 + jj;
                Fs[row*132 + jj] = (gl >= 0 && gl < NL) ? fr[gl] : 0.f;
            }
        }
        __syncthreads();

#pragma unroll
        for (int kk = 0; kk < 8; kk++) {
            float f[12];
            const float4* frow = (const float4*)(Fs + kk*132);
            float4 fa = frow[2*tx], fbv = frow[2*tx+1], fc = frow[2*tx+2];
            f[0]=fa.x; f[1]=fa.y; f[2]=fa.z; f[3]=fa.w;
            f[4]=fbv.x; f[5]=fbv.y; f[6]=fbv.z; f[7]=fbv.w;
            f[8]=fc.x; f[9]=fc.y;
            float wv[3][8];
#pragma unroll
            for (int t = 0; t < 3; t++) {
                const float4* wrow = (const float4*)(Ws + (t*8+kk)*128);
                float4 wa = wrow[2*ty], wb = wrow[2*ty+1];
                wv[t][0]=wa.x; wv[t][1]=wa.y; wv[t][2]=wa.z; wv[t][3]=wa.w;
                wv[t][4]=wb.x; wv[t][5]=wb.y; wv[t][6]=wb.z; wv[t][7]=wb.w;
            }
#pragma unroll
            for (int i = 0; i < 8; i++)
#pragma unroll
                for (int j = 0; j < 8; j++) {
                    acc[i][j] += wv[0][i]*f[j];
                    acc[i][j] += wv[1][i]*f[j+1];
                    acc[i][j] += wv[2][i]*f[j+2];
                }
        }
        __syncthreads();
    }

    float* hb = g_h + (size_t)b*NC*NL;
#pragma unroll
    for (int i = 0; i < 8; i++) {
        int o = o0 + 8*ty + i;
        float bv = __ldg(bias + o);
        float* hr = hb + (size_t)o*NL + l0 + 8*tx;
#pragma unroll
        for (int j = 0; j < 8; j++) hr[j] = fmaxf(acc[i][j] + bv, 0.f);
    }
}

// ---------------------------------------------------------------------------
// Kernel 2: obj/reg heads + box decode + sigmoid scores.
// One thread handles 2 positions. 21x512 weights in smem.
// ---------------------------------------------------------------------------
__global__ __launch_bounds__(256)
void proj_kernel(const float* __restrict__ obj_w, const float* __restrict__ obj_b,
                 const float* __restrict__ reg_w, const float* __restrict__ reg_b,
                 float* __restrict__ out) {
    __shared__ float ws[21*512];
    const int b  = blockIdx.y;
    const int l0 = blockIdx.x * 512;
    const int tid = threadIdx.x;

    for (int i = tid; i < 7*512;  i += 256) ws[i] = obj_w[i];
    for (int i = tid; i < 14*512; i += 256) ws[3584 + i] = reg_w[i];
    __syncthreads();

    float acc[21][2];
#pragma unroll
    for (int a = 0; a < 21; a++) { acc[a][0] = 0.f; acc[a][1] = 0.f; }

    const float* hb = g_h + (size_t)b*NC*NL + l0 + tid;
#pragma unroll 4
    for (int c = 0; c < NC; c++) {
        float h0 = hb[(size_t)c*NL];
        float h1 = hb[(size_t)c*NL + 256];
#pragma unroll
        for (int a = 0; a < 21; a++) {
            float wv = ws[a*512 + c];
            acc[a][0] += wv*h0;
            acc[a][1] += wv*h1;
        }
    }

#pragma unroll
    for (int r = 0; r < 2; r++) {
        int l = l0 + 256*r + tid;
#pragma unroll
        for (int a = 0; a < NA; a++) {
            float ol = acc[a][r] + __ldg(obj_b + a);
            size_t n = (size_t)b*NPA + (size_t)l*NA + a;
            out[OFF_OBJ + n] = ol;
            float sc = 1.f/(1.f + expf(-ol));
            g_scores[n] = sc;
            float tc = acc[7 + 2*a][r]   + __ldg(reg_b + 2*a);
            float tw = acc[7 + 2*a+1][r] + __ldg(reg_b + 2*a + 1);
            out[OFF_REG + 2*n]     = tc;
            out[OFF_REG + 2*n + 1] = tw;
            float len = c_lens[a];
            float twc = fminf(fmaxf(tw, -10.f), 10.f);
            float cc = ((float)l + 0.5f) + tc*len;
            float ww = len * expf(twc);
            float s = fminf(fmaxf(cc - 0.5f*ww, 0.f), 8192.f);
            float e = fminf(fmaxf(cc + 0.5f*ww, 0.f), 8192.f);
            e = fminf(fmaxf(e, s + 1e-3f), 8192.f);
            s = fmaxf(fminf(s, e - 1e-3f), 0.f);
            g_boxes[2*n]     = s;
            g_boxes[2*n + 1] = e;
        }
    }
}

// ---------------------------------------------------------------------------
// Kernel 3: anchors (exact in f32: all values multiples of 0.5 < 16384)
// ---------------------------------------------------------------------------
__global__ void anchors_kernel(float* __restrict__ out) {
    int n = blockIdx.x*blockDim.x + threadIdx.x;
    if (n < NPA) {
        int l = n / NA, a = n % NA;
        float cen = (float)l + 0.5f, half = 0.5f*c_lens[a];
        out[OFF_ANCH + 2*n]     = cen - half;
        out[OFF_ANCH + 2*n + 1] = cen + half;
    }
}

// ---------------------------------------------------------------------------
// Kernel 4: per-batch exact top-600 (with jax tie-breaking) + greedy NMS +
// top-100 output. One block per batch, 512 threads.
// ---------------------------------------------------------------------------
__global__ __launch_bounds__(512)
void topk_nms_kernel(float* __restrict__ out) {
    const int b = blockIdx.x;
    const int tid = threadIdx.x;

    __shared__ unsigned long long keys[1024];
    __shared__ int   eq[1024];
    __shared__ float sbox[PRE_K*2];
    __shared__ float ssc[PRE_K];
    __shared__ int   skept[POST_K];
    __shared__ int   s_cnt, s_g, s_e, s_nk;

    const float* sc = g_scores + (size_t)b*NPA;

    // ---- binary search for V = 600th-largest score (as uint bits) ----
    unsigned lo = 0u, hi = 0x3F800001u;   // scores in (0, 1]; g(lo)>=600 > g(hi)=0
    for (int it = 0; it < 31 && (hi - lo) > 1u; ++it) {
        unsigned mid = lo + ((hi - lo) >> 1);
        if (tid == 0) s_cnt = 0;
        __syncthreads();
        int c = 0;
        for (int p = tid; p < NPA; p += 512)
            c += (__float_as_uint(sc[p]) >= mid) ? 1 : 0;
#pragma unroll
        for (int o = 16; o; o >>= 1) c += __shfl_down_sync(0xffffffffu, c, o);
        if ((tid & 31) == 0) atomicAdd(&s_cnt, c);
        __syncthreads();
        int total = s_cnt;
        if (total >= PRE_K) lo = mid; else hi = mid;
        __syncthreads();
    }
    const unsigned V = lo;

    // ---- compact: strictly-greater entries + equal-to-V indices ----
    if (tid == 0) { s_g = 0; s_e = 0; }
    __syncthreads();
    for (int p = tid; p < NPA; p += 512) {
        unsigned bits = __float_as_uint(sc[p]);
        if (bits > V) {
            int q = atomicAdd(&s_g, 1);
            if (q < 1024)
                keys[q] = ((unsigned long long)bits << 32) |
                          (unsigned long long)(0xFFFFFFFFu - (unsigned)p);
        } else if (bits == V) {
            int q = atomicAdd(&s_e, 1);
            if (q < 1024) eq[q] = p;
        }
    }
    __syncthreads();
    int ng = s_g < 1024 ? s_g : 1024;   // guaranteed < 600
    int ne = s_e < 1024 ? s_e : 1024;
    for (int i = tid; i < 1024; i += 512) {
        if (i >= ng) {
            int e = i - ng;
            keys[i] = (e < ne)
                ? (((unsigned long long)V << 32) |
                   (unsigned long long)(0xFFFFFFFFu - (unsigned)eq[e]))
                : 0ULL;
        }
    }

    // ---- bitonic sort 1024, descending (value desc, index asc) ----
    for (int k = 2; k <= 1024; k <<= 1) {
        for (int j = k >> 1; j > 0; j >>= 1) {
            __syncthreads();
            for (int i = tid; i < 1024; i += 512) {
                int l = i ^ j;
                if (l > i) {
                    unsigned long long a = keys[i], bb = keys[l];
                    bool up = ((i & k) == 0);
                    bool sw = up ? (a < bb) : (a > bb);
                    if (sw) { keys[i] = bb; keys[l] = a; }
                }
            }
        }
    }
    __syncthreads();

    // ---- gather top-600 boxes & scores ----
    for (int i = tid; i < PRE_K; i += 512) {
        unsigned long long kv = keys[i];
        unsigned bits = (unsigned)(kv >> 32);
        if (bits == 0u) {   // pathological underflow guard
            ssc[i] = 0.f; sbox[2*i] = 0.f; sbox[2*i+1] = 0.f;
        } else {
            unsigned ridx = 0xFFFFFFFFu - (unsigned)(kv & 0xFFFFFFFFull);
            ssc[i] = __uint_as_float(bits);
            const float* bp = g_boxes + ((size_t)b*NPA + ridx)*2;
            sbox[2*i]   = bp[0];
            sbox[2*i+1] = bp[1];
        }
    }
    __syncthreads();

    // ---- suppression bitmask: m[i][j<i] = iou > 0.5 ----
    for (int i = tid; i < PRE_K; i += 512) {
        float si = sbox[2*i], ei = sbox[2*i+1];
        float wi = ei - si;
        for (int w = 0; w < NMW; w++) {
            unsigned m = 0;
            int jbase = w*32;
            int jmax = i - jbase; if (jmax > 32) jmax = 32;
            for (int jj = 0; jj < jmax; jj++) {
                int j = jbase + jj;
                float sj = sbox[2*j], ej = sbox[2*j+1];
                float inter = fmaxf(fminf(ei, ej) - fmaxf(si, sj), 0.f);
                float uni = wi + (ej - sj) - inter;
                float iou = inter / fmaxf(uni, 1e-6f);
                if (iou > 0.5f) m |= (1u << jj);
            }
            g_mask[((size_t)b*PRE_K + i)*NMW + w] = m;
        }
    }
    __syncthreads();

    // ---- greedy serial scan (one warp; lane j holds keep-word j) ----
    if (tid < 32) {
        int lane = tid;
        unsigned keepw = 0;
        int nk = 0;
        for (int i = 0; i < PRE_K; i++) {
            unsigned mw = (lane < NMW)
                ? g_mask[((size_t)b*PRE_K + i)*NMW + lane] : 0u;
            bool sup = __any_sync(0xffffffffu, (mw & keepw) != 0u);
            bool val = (ssc[i] >= 0.1f);
            if (val && !sup) {
                if (lane == (i >> 5)) keepw |= (1u << (i & 31));
                if (lane == 0 && nk < POST_K) skept[nk] = i;
                nk++;
            }
        }
        if (lane == 0) s_nk = (nk < POST_K) ? nk : POST_K;
    }
    __syncthreads();

    // ---- emit props / pscores / pmask ----
    int nk = s_nk;
    for (int r = tid; r < POST_K; r += 512) {
        bool on = r < nk;
        int i = on ? skept[r] : 0;
        float sv = on ? ssc[i] : 0.f;
        float b0 = on ? sbox[2*i]   : 0.f;
        float b1 = on ? sbox[2*i+1] : 0.f;
        size_t base = (size_t)b*POST_K + r;
        out[OFF_PROPS + 2*base]     = b0;
        out[OFF_PROPS + 2*base + 1] = b1;
        out[OFF_PSC  + base] = sv;
        out[OFF_PMASK + base] = on ? 1.0f : 0.0f;
    }
}

// ---------------------------------------------------------------------------
extern "C" void kernel_launch(void* const* d_in, const int* in_sizes, int n_in,
                              void* d_out, int out_size) {
    const float* feat   = (const float*)d_in[0];
    const float* conv_w = (const float*)d_in[1];
    const float* conv_b = (const float*)d_in[2];
    const float* obj_w  = (const float*)d_in[3];
    const float* obj_b  = (const float*)d_in[4];
    const float* reg_w  = (const float*)d_in[5];
    const float* reg_b  = (const float*)d_in[6];
    float* out = (float*)d_out;

    dim3 cgrid(NL/128, NC/128, NB);           // 64 x 4 x 8 = 2048 blocks
    conv_kernel<<<cgrid, 256>>>(feat, conv_w, conv_b);

    dim3 pgrid(NL/512, NB);                   // 16 x 8 = 128 blocks
    proj_kernel<<<pgrid, 256>>>(obj_w, obj_b, reg_w, reg_b, out);

    anchors_kernel<<<(NPA + 255)/256, 256>>>(out);

    topk_nms_kernel<<<NB, 512>>>(out);
}